// round 2
// baseline (speedup 1.0000x reference)
#include <cuda_runtime.h>

// Problem constants
#define NCODES 1024
#define DIM    64
#define BSZ    16
#define TLEN   16384
#define NSAMP  (BSZ * TLEN)          // 262144
#define ZQ_ELEMS (BSZ * DIM * TLEN)  // 16777216

// Output layout (float32, concatenated in reference return order):
// [0, ZQ_ELEMS)                    z_q  (b, d, t)
// [ZQ_ELEMS, ZQ_ELEMS+NSAMP)       indices (b, t) as float
// then 4 scalars: vq_loss, codebook_loss, commitment_loss, utilization
#define IDX_OFF  ZQ_ELEMS
#define SCAL_OFF (ZQ_ELEMS + NSAMP)

// Dynamic smem layout for vq_argmin_kernel
#define ZS_BYTES   (64 * 128 * 4)              // 32768
#define CS_BYTES   (64 * 132 * 4)              // 33792
#define SMEM_TOTAL (ZS_BYTES + CS_BYTES + 128 * 4 + 128 * 4)  // 67584 + 1024 = 68608

// Device scratch (no allocations allowed)
__device__ float  g_c_sq[NCODES];
__device__ int    g_idx[NSAMP];
__device__ int    g_flags[NCODES];
__device__ double g_loss;

typedef unsigned long long u64;

__device__ __forceinline__ u64 pack2(float lo, float hi) {
    u64 r; asm("mov.b64 %0, {%1, %2};" : "=l"(r) : "f"(lo), "f"(hi)); return r;
}
__device__ __forceinline__ void unpack2(u64 v, float& lo, float& hi) {
    asm("mov.b64 {%0, %1}, %2;" : "=f"(lo), "=f"(hi) : "l"(v));
}
__device__ __forceinline__ u64 fma2(u64 a, u64 b, u64 c) {
    u64 d; asm("fma.rn.f32x2 %0, %1, %2, %3;" : "=l"(d) : "l"(a), "l"(b), "l"(c)); return d;
}

// ---------------------------------------------------------------------------
// Kernel 0: c_sq per code, zero flags, zero loss accumulator.
// ---------------------------------------------------------------------------
__global__ void prep_kernel(const float* __restrict__ codebook) {
    int j = threadIdx.x;  // 1024 threads
    const float* r = codebook + (size_t)j * DIM;
    float s = 0.f;
    #pragma unroll
    for (int k = 0; k < DIM; k++) {
        float c = r[k];
        s = __fadd_rn(s, __fmul_rn(c, c));
    }
    g_c_sq[j]  = s;
    g_flags[j] = 0;
    if (j == 0) g_loss = 0.0;
}

// ---------------------------------------------------------------------------
// Kernel B: fused distance-GEMM + argmin.
// CTA: 128 samples (consecutive t for one b) x all 1024 codes, K = 64.
// 256 threads, 8x8 register tile per thread, FFMA2 packed fp32.
// dist replicates reference rounding: R( R(z_sq + c_sq) - 2*dot ).
// Dynamic smem (67.6KB > 48KB static ptxas cap).
// ---------------------------------------------------------------------------
__global__ void __launch_bounds__(256, 2)
vq_argmin_kernel(const float* __restrict__ z_e,
                 const float* __restrict__ codebook,
                 float* __restrict__ out_idx_f) {
    extern __shared__ char smem_raw[];
    float (*zs)[128]  = (float(*)[128])(smem_raw);                 // [k][m] 32KB
    float (*cs)[132]  = (float(*)[132])(smem_raw + ZS_BYTES);      // [k][n] 33.8KB
    float* zsq_s = (float*)(smem_raw + ZS_BYTES + CS_BYTES);
    float* csq_s = zsq_s + 128;

    const int b   = blockIdx.y;
    const int t0  = blockIdx.x * 128;
    const int tid = threadIdx.x;
    const int tx  = tid & 15;   // code group
    const int ty  = tid >> 4;   // sample group

    // Load z tile: z_e[b][k][t0 + m], coalesced float4 per feature row.
    const float* zbase = z_e + ((size_t)b * DIM) * TLEN + t0;
    #pragma unroll
    for (int i = tid; i < 64 * 32; i += 256) {
        int k = i >> 5, q = i & 31;
        float4 v = *(const float4*)(zbase + (size_t)k * TLEN + q * 4);
        *(float4*)(&zs[k][q * 4]) = v;
    }
    __syncthreads();

    // z_sq per sample: sequential k, squares rounded separately (mimic ref).
    if (tid < 128) {
        float s = 0.f;
        #pragma unroll
        for (int k = 0; k < DIM; k++) {
            float z = zs[k][tid];
            s = __fadd_rn(s, __fmul_rn(z, z));
        }
        zsq_s[tid] = s;
    }

    float best_val[8];
    int   best_idx[8];
    #pragma unroll
    for (int i = 0; i < 8; i++) { best_val[i] = 3.4e38f; best_idx[i] = NCODES; }

    for (int c0 = 0; c0 < NCODES; c0 += 128) {
        __syncthreads();  // protect cs/csq_s against previous iteration readers

        // Transpose-load 128 codes: cs[k][n] = codebook[c0+n][k]
        {
            int n = tid >> 1, h = tid & 1;  // 2 threads per code
            const float4* src = (const float4*)(codebook + ((size_t)(c0 + n)) * DIM + h * 32);
            #pragma unroll
            for (int j = 0; j < 8; j++) {
                float4 v = src[j];
                int k = h * 32 + j * 4;
                cs[k + 0][n] = v.x; cs[k + 1][n] = v.y;
                cs[k + 2][n] = v.z; cs[k + 3][n] = v.w;
            }
        }
        if (tid < 128) csq_s[tid] = g_c_sq[c0 + tid];
        __syncthreads();

        // 8x8 dot tile over K=64, packed over code pairs.
        u64 acc[8][4];
        #pragma unroll
        for (int i = 0; i < 8; i++)
            #pragma unroll
            for (int jp = 0; jp < 4; jp++) acc[i][jp] = 0ULL;

        #pragma unroll 4
        for (int k = 0; k < 64; k++) {
            float4 za = *(const float4*)&zs[k][ty * 8];
            float4 zb = *(const float4*)&zs[k][ty * 8 + 4];
            float4 ca = *(const float4*)&cs[k][tx * 8];
            float4 cb = *(const float4*)&cs[k][tx * 8 + 4];
            u64 cp[4];
            cp[0] = pack2(ca.x, ca.y);
            cp[1] = pack2(ca.z, ca.w);
            cp[2] = pack2(cb.x, cb.y);
            cp[3] = pack2(cb.z, cb.w);
            float zf[8] = {za.x, za.y, za.z, za.w, zb.x, zb.y, zb.z, zb.w};
            #pragma unroll
            for (int i = 0; i < 8; i++) {
                u64 zz = pack2(zf[i], zf[i]);
                #pragma unroll
                for (int jp = 0; jp < 4; jp++)
                    acc[i][jp] = fma2(zz, cp[jp], acc[i][jp]);
            }
        }

        // Epilogue: dist = R(R(z_sq + c_sq) - 2*dot), first-index tie-break.
        #pragma unroll
        for (int i = 0; i < 8; i++) {
            float zq = zsq_s[ty * 8 + i];
            #pragma unroll
            for (int jp = 0; jp < 4; jp++) {
                float d0, d1;
                unpack2(acc[i][jp], d0, d1);
                int n0 = tx * 8 + jp * 2;
                float dist0 = fmaf(-2.f, d0, __fadd_rn(zq, csq_s[n0]));
                float dist1 = fmaf(-2.f, d1, __fadd_rn(zq, csq_s[n0 + 1]));
                int code0 = c0 + n0, code1 = code0 + 1;
                if (dist0 < best_val[i] || (dist0 == best_val[i] && code0 < best_idx[i])) {
                    best_val[i] = dist0; best_idx[i] = code0;
                }
                if (dist1 < best_val[i] || (dist1 == best_val[i] && code1 < best_idx[i])) {
                    best_val[i] = dist1; best_idx[i] = code1;
                }
            }
        }
    }

    // Cross-thread reduction over the 16 tx groups (reuse zs as scratch).
    __syncthreads();
    float* rv = &zs[0][0];        // 128 x 16 floats (8KB)
    int*   ri = (int*)&zs[16][0]; // 128 x 16 ints   (8KB)
    #pragma unroll
    for (int i = 0; i < 8; i++) {
        rv[(ty * 8 + i) * 16 + tx] = best_val[i];
        ri[(ty * 8 + i) * 16 + tx] = best_idx[i];
    }
    __syncthreads();
    if (tid < 128) {
        float bv = rv[tid * 16];
        int   bi = ri[tid * 16];
        #pragma unroll
        for (int x = 1; x < 16; x++) {
            float v  = rv[tid * 16 + x];
            int   id = ri[tid * 16 + x];
            if (v < bv || (v == bv && id < bi)) { bv = v; bi = id; }
        }
        int n = b * TLEN + t0 + tid;
        g_idx[n]     = bi;
        g_flags[bi]  = 1;
        out_idx_f[n] = (float)bi;
    }
}

// ---------------------------------------------------------------------------
// Kernel C: z_q gather-write + sum of (z_q - z_e)^2.
// One block per (k, b) row of 16384 elements; codebook column staged in smem.
// ---------------------------------------------------------------------------
__global__ void __launch_bounds__(256)
zq_loss_kernel(const float* __restrict__ z_e,
               const float* __restrict__ codebook,
               float* __restrict__ zq_out) {
    const int k = blockIdx.x;   // 0..63
    const int b = blockIdx.y;   // 0..15
    const int tid = threadIdx.x;

    __shared__ float col[NCODES];
    for (int j = tid; j < NCODES; j += 256) col[j] = codebook[(size_t)j * DIM + k];
    __syncthreads();

    const float* zrow   = z_e    + ((size_t)b * DIM + k) * TLEN;
    float*       orow   = zq_out + ((size_t)b * DIM + k) * TLEN;
    const int*   idxrow = g_idx  + (size_t)b * TLEN;

    float s = 0.f;
    for (int t = tid; t < TLEN; t += 256) {
        int   idx = idxrow[t];
        float v   = col[idx];
        orow[t] = v;
        float d = v - zrow[t];
        s = fmaf(d, d, s);
    }

    __shared__ double rs[256];
    rs[tid] = (double)s;
    __syncthreads();
    for (int off = 128; off > 0; off >>= 1) {
        if (tid < off) rs[tid] += rs[tid + off];
        __syncthreads();
    }
    if (tid == 0) atomicAdd(&g_loss, rs[0]);
}

// ---------------------------------------------------------------------------
// Kernel E: utilization + loss scalars.
// ---------------------------------------------------------------------------
__global__ void finalize_kernel(float* __restrict__ out) {
    __shared__ int cnt[1024];
    int tid = threadIdx.x;
    cnt[tid] = g_flags[tid];
    __syncthreads();
    for (int off = 512; off > 0; off >>= 1) {
        if (tid < off) cnt[tid] += cnt[tid + off];
        __syncthreads();
    }
    if (tid == 0) {
        float m = (float)(g_loss / (double)ZQ_ELEMS);
        out[SCAL_OFF + 0] = m + 0.25f * m;           // vq_loss
        out[SCAL_OFF + 1] = m;                        // codebook_loss
        out[SCAL_OFF + 2] = m;                        // commitment_loss
        out[SCAL_OFF + 3] = (float)cnt[0] / (float)NCODES;  // utilization
    }
}

// ---------------------------------------------------------------------------
extern "C" void kernel_launch(void* const* d_in, const int* in_sizes, int n_in,
                              void* d_out, int out_size) {
    const float* z_e      = (const float*)d_in[0];
    const float* codebook = (const float*)d_in[1];
    float* out = (float*)d_out;

    static bool attr_set = false;
    if (!attr_set) {
        cudaFuncSetAttribute(vq_argmin_kernel,
                             cudaFuncAttributeMaxDynamicSharedMemorySize,
                             SMEM_TOTAL);
        attr_set = true;
    }

    prep_kernel<<<1, 1024>>>(codebook);
    vq_argmin_kernel<<<dim3(TLEN / 128, BSZ), 256, SMEM_TOTAL>>>(z_e, codebook, out + IDX_OFF);
    zq_loss_kernel<<<dim3(DIM, BSZ), 256>>>(z_e, codebook, out);
    finalize_kernel<<<1, 1024>>>(out);
}

// round 5
// speedup vs baseline: 2.1340x; 2.1340x over previous
#include <cuda_runtime.h>
#include <cuda_fp16.h>
#include <cstdint>

// Problem constants
#define NCODES 1024
#define DIM    64
#define BSZ    16
#define TLEN   16384
#define NSAMP  (BSZ * TLEN)          // 262144
#define ZQ_ELEMS (BSZ * DIM * TLEN)  // 16777216

#define IDX_OFF  ZQ_ELEMS
#define SCAL_OFF (ZQ_ELEMS + NSAMP)

typedef unsigned long long u64;

// ---------------- device globals (no dynamic alloc allowed) ----------------
__device__ float    g_c_sq[NCODES];
__device__ int      g_idx[NSAMP];
__device__ int      g_flags[NCODES];
__device__ double   g_loss;
__device__ float    g_zsq[NSAMP];
__device__ u64      g_best[NSAMP];
// A fragments: [t16 tile (16384)][kstep 4][split 2][lane 32][4 u32] = 64MB
__device__ uint32_t g_afrag[(size_t)16384 * 4 * 2 * 32 * 4];
// B fragments: [group 2][nb 64][kstep 4][split 2][lane 32][2 u32] = 256KB
__device__ uint32_t g_bfrag[2 * 64 * 4 * 2 * 32 * 2];

// fp16 hi/lo split pack helpers
__device__ __forceinline__ void split_pair(float x, float y, uint32_t& hi, uint32_t& lo) {
    __half hx = __float2half_rn(x);
    __half hy = __float2half_rn(y);
    float  rx = x - __half2float(hx);
    float  ry = y - __half2float(hy);
    __half lx = __float2half_rn(rx);
    __half ly = __float2half_rn(ry);
    hi = (uint32_t)__half_as_ushort(hx) | ((uint32_t)__half_as_ushort(hy) << 16);
    lo = (uint32_t)__half_as_ushort(lx) | ((uint32_t)__half_as_ushort(ly) << 16);
}

// m16n8k16 row.col f32.f16.f16.f32
#define HMMA(d, a, b0, b1) \
    asm volatile("mma.sync.aligned.m16n8k16.row.col.f32.f16.f16.f32 " \
        "{%0,%1,%2,%3}, {%4,%5,%6,%7}, {%8,%9}, {%0,%1,%2,%3};" \
        : "+f"((d)[0]), "+f"((d)[1]), "+f"((d)[2]), "+f"((d)[3]) \
        : "r"((a)[0]), "r"((a)[1]), "r"((a)[2]), "r"((a)[3]), "r"(b0), "r"(b1))

// ---------------------------------------------------------------------------
// prep: c_sq (exact sequential rounding), codebook fp16 hi/lo B-fragments
//       (codes scaled by 512), zero flags + loss.
// ---------------------------------------------------------------------------
__global__ void __launch_bounds__(1024)
prep_codebook(const float* __restrict__ codebook) {
    int j = threadIdx.x;  // 1024 threads = 1 per code
    const float* r = codebook + (size_t)j * DIM;
    float s = 0.f;
    #pragma unroll
    for (int k = 0; k < DIM; k++) {
        float c = r[k];
        s = __fadd_rn(s, __fmul_rn(c, c));
    }
    g_c_sq[j]  = s;
    g_flags[j] = 0;
    if (j == 0) g_loss = 0.0;

    int group = j >> 9;
    int nbl   = (j >> 3) & 63;
    int nin   = j & 7;
    uint32_t* base = g_bfrag + (size_t)group * 32768;
    for (int ks = 0; ks < 4; ks++) {
        for (int t = 0; t < 4; t++) {
            int lane = nin * 4 + t;
            int kd = ks * 16 + 2 * t;
            uint32_t h0, l0, h1, l1;
            split_pair(r[kd]     * 512.f, r[kd + 1] * 512.f, h0, l0);
            split_pair(r[kd + 8] * 512.f, r[kd + 9] * 512.f, h1, l1);
            uint32_t o_hi = ((uint32_t)(nbl * 4 + ks) * 2 + 0) * 64 + lane * 2;
            uint32_t o_lo = ((uint32_t)(nbl * 4 + ks) * 2 + 1) * 64 + lane * 2;
            base[o_hi]     = h0;
            base[o_hi + 1] = h1;
            base[o_lo]     = l0;
            base[o_lo + 1] = l1;
        }
    }
}

// ---------------------------------------------------------------------------
// z split: per-sample zsq (R2-exact sequential rounding), fp16 hi/lo A-frags
// in fragment layout, g_best init. Block = 128 samples = 8 sample-tiles.
// ---------------------------------------------------------------------------
__global__ void __launch_bounds__(128)
z_split_kernel(const float* __restrict__ z_e) {
    __shared__ uint32_t buf[8192];   // 8 tiles x 1024 u32 = 32KB
    const int tid = threadIdx.x;
    const int s   = blockIdx.x * 128 + tid;
    const int tl  = tid >> 4;        // local tile 0..7
    const int r   = tid & 15;        // row in tile
    const int b   = s / TLEN;
    const int t   = s % TLEN;

    const float* zp = z_e + (size_t)b * DIM * TLEN + t;
    float zv[64];
    #pragma unroll
    for (int k = 0; k < DIM; k++) zv[k] = zp[(size_t)k * TLEN];

    float zsq = 0.f;
    #pragma unroll
    for (int k = 0; k < DIM; k++)
        zsq = __fadd_rn(zsq, __fmul_rn(zv[k], zv[k]));
    g_zsq[s]  = zsq;
    g_best[s] = ~0ull;

    const int rlo = (r < 8) ? 0 : 1;   // a0/a1 vs a2/a3 reg slot
    const int rl  = r & 7;
    #pragma unroll
    for (int ks = 0; ks < 4; ks++) {
        #pragma unroll
        for (int tt = 0; tt < 4; tt++) {
            int lane = rl * 4 + tt;
            int kd = ks * 16 + 2 * tt;
            uint32_t h0, l0, h1, l1;
            split_pair(zv[kd],     zv[kd + 1], h0, l0);
            split_pair(zv[kd + 8], zv[kd + 9], h1, l1);
            uint32_t bh = (((uint32_t)(tl * 4 + ks) * 2 + 0) * 32 + lane) * 4;
            uint32_t bl = (((uint32_t)(tl * 4 + ks) * 2 + 1) * 32 + lane) * 4;
            buf[bh + rlo]     = h0;   // a0 or a1 (k low half)
            buf[bh + rlo + 2] = h1;   // a2 or a3 (k high half)
            buf[bl + rlo]     = l0;
            buf[bl + rlo + 2] = l1;
        }
    }
    __syncthreads();
    uint4* dst = (uint4*)g_afrag + (size_t)blockIdx.x * 2048;
    const uint4* srcb = (const uint4*)buf;
    #pragma unroll
    for (int i = 0; i < 16; i++) dst[tid + i * 128] = srcb[tid + i * 128];
}

// ---------------------------------------------------------------------------
// Main kernel: HMMA fp16 3-pass distance GEMM + fused argmin.
// grid (512, 2): x = 512-sample block, y = code group (512 codes in smem).
// Warp = 32 samples resident in A-frags; streams 64 nb of 8 codes.
// ---------------------------------------------------------------------------
#define VQ_SMEM (131072 + 2048)

__global__ void __launch_bounds__(512, 1)
vq_mma_kernel() {
    extern __shared__ __align__(16) uint32_t sb[];   // [32768] B frags + 512 csq
    const int tid   = threadIdx.x;
    const int lane  = tid & 31;
    const int w     = tid >> 5;
    const int group = blockIdx.y;

    // stage B fragments (128KB) + csq (2KB)
    {
        const uint4* src = (const uint4*)(g_bfrag + (size_t)group * 32768);
        uint4* dst = (uint4*)sb;
        #pragma unroll
        for (int i = 0; i < 16; i++) dst[tid + i * 512] = src[tid + i * 512];
        ((float*)(sb + 32768))[tid] = g_c_sq[group * 512 + tid];
    }
    __syncthreads();
    const float* csq_s = (const float*)(sb + 32768);

    const int wt    = blockIdx.x * 16 + w;    // warp-tile id (32 samples)
    const int sbase = wt * 32;

    // resident A fragments: [tile2][kstep4][split2][4]
    uint32_t A[2][4][2][4];
    #pragma unroll
    for (int tl = 0; tl < 2; tl++)
        #pragma unroll
        for (int ks = 0; ks < 4; ks++)
            #pragma unroll
            for (int sp = 0; sp < 2; sp++) {
                const uint4* p = (const uint4*)g_afrag
                    + (((size_t)(wt * 2 + tl) * 4 + ks) * 2 + sp) * 32 + lane;
                uint4 v = *p;
                A[tl][ks][sp][0] = v.x; A[tl][ks][sp][1] = v.y;
                A[tl][ks][sp][2] = v.z; A[tl][ks][sp][3] = v.w;
            }

    float zs[4];
    #pragma unroll
    for (int q = 0; q < 4; q++) zs[q] = g_zsq[sbase + (lane >> 2) + q * 8];

    float bv[4] = {3.4e38f, 3.4e38f, 3.4e38f, 3.4e38f};
    int   bi[4] = {0, 0, 0, 0};

    for (int nb = 0; nb < 64; nb++) {
        uint32_t B[4][2][2];
        #pragma unroll
        for (int ks = 0; ks < 4; ks++)
            #pragma unroll
            for (int sp = 0; sp < 2; sp++) {
                uint2 t2 = *(const uint2*)(sb + ((nb * 4 + ks) * 2 + sp) * 64 + lane * 2);
                B[ks][sp][0] = t2.x; B[ks][sp][1] = t2.y;
            }
        float2 cq = *(const float2*)(csq_s + nb * 8 + (lane & 3) * 2);

        float acc[2][4] = {{0.f, 0.f, 0.f, 0.f}, {0.f, 0.f, 0.f, 0.f}};
        #pragma unroll
        for (int tl = 0; tl < 2; tl++)
            #pragma unroll
            for (int ks = 0; ks < 4; ks++) {
                HMMA(acc[tl], A[tl][ks][0], B[ks][0][0], B[ks][0][1]);  // zhi*chi
                HMMA(acc[tl], A[tl][ks][1], B[ks][0][0], B[ks][0][1]);  // zlo*chi
                HMMA(acc[tl], A[tl][ks][0], B[ks][1][0], B[ks][1][1]);  // zhi*clo
            }

        // epilogue: dist = R( R(zsq+csq) - 2*dot ), dot = acc/512
        const int j0 = group * 512 + nb * 8 + (lane & 3) * 2;
        #pragma unroll
        for (int tl = 0; tl < 2; tl++)
            #pragma unroll
            for (int h = 0; h < 2; h++) {
                int slot = tl * 2 + h;
                float s0 = __fadd_rn(zs[slot], cq.x);
                float s1 = __fadd_rn(zs[slot], cq.y);
                float dA = fmaf(-0.00390625f, acc[tl][h * 2 + 0], s0);
                float dB = fmaf(-0.00390625f, acc[tl][h * 2 + 1], s1);
                if (dA < bv[slot]) { bv[slot] = dA; bi[slot] = j0; }
                if (dB < bv[slot]) { bv[slot] = dB; bi[slot] = j0 + 1; }
            }
    }

    // cross-lane reduce over l%4 (lexicographic (val, idx) min)
    #pragma unroll
    for (int slot = 0; slot < 4; slot++) {
        #pragma unroll
        for (int off = 1; off <= 2; off <<= 1) {
            float v  = __shfl_xor_sync(0xFFFFFFFF, bv[slot], off);
            int   id = __shfl_xor_sync(0xFFFFFFFF, bi[slot], off);
            if (v < bv[slot] || (v == bv[slot] && id < bi[slot])) {
                bv[slot] = v; bi[slot] = id;
            }
        }
        if ((lane & 3) == 0) {
            int sample = sbase + (lane >> 2) + slot * 8;
            u64 packed = ((u64)__float_as_uint(bv[slot]) << 32) | (uint32_t)bi[slot];
            atomicMin(&g_best[sample], packed);
        }
    }
}

// ---------------------------------------------------------------------------
// idx finalize: unpack g_best -> g_idx, out indices, utilization flags
// ---------------------------------------------------------------------------
__global__ void __launch_bounds__(512)
idx_final_kernel(float* __restrict__ out_idx_f) {
    int n = blockIdx.x * 512 + threadIdx.x;
    u64 p = g_best[n];
    int idx = (int)(uint32_t)(p & 0xffffffffu);
    g_idx[n]      = idx;
    g_flags[idx]  = 1;
    out_idx_f[n]  = (float)idx;
}

// ---------------------------------------------------------------------------
// z_q gather-write + sum of (z_q - z_e)^2  (unchanged, R2-verified)
// ---------------------------------------------------------------------------
__global__ void __launch_bounds__(256)
zq_loss_kernel(const float* __restrict__ z_e,
               const float* __restrict__ codebook,
               float* __restrict__ zq_out) {
    const int k = blockIdx.x;
    const int b = blockIdx.y;
    const int tid = threadIdx.x;

    __shared__ float col[NCODES];
    for (int j = tid; j < NCODES; j += 256) col[j] = codebook[(size_t)j * DIM + k];
    __syncthreads();

    const float* zrow   = z_e    + ((size_t)b * DIM + k) * TLEN;
    float*       orow   = zq_out + ((size_t)b * DIM + k) * TLEN;
    const int*   idxrow = g_idx  + (size_t)b * TLEN;

    float s = 0.f;
    for (int t = tid; t < TLEN; t += 256) {
        int   idx = idxrow[t];
        float v   = col[idx];
        orow[t] = v;
        float d = v - zrow[t];
        s = fmaf(d, d, s);
    }

    __shared__ double rs[256];
    rs[tid] = (double)s;
    __syncthreads();
    for (int off = 128; off > 0; off >>= 1) {
        if (tid < off) rs[tid] += rs[tid + off];
        __syncthreads();
    }
    if (tid == 0) atomicAdd(&g_loss, rs[0]);
}

__global__ void __launch_bounds__(1024)
finalize_kernel(float* __restrict__ out) {
    __shared__ int cnt[1024];
    int tid = threadIdx.x;
    cnt[tid] = g_flags[tid];
    __syncthreads();
    for (int off = 512; off > 0; off >>= 1) {
        if (tid < off) cnt[tid] += cnt[tid + off];
        __syncthreads();
    }
    if (tid == 0) {
        float m = (float)(g_loss / (double)ZQ_ELEMS);
        out[SCAL_OFF + 0] = m + 0.25f * m;
        out[SCAL_OFF + 1] = m;
        out[SCAL_OFF + 2] = m;
        out[SCAL_OFF + 3] = (float)cnt[0] / (float)NCODES;
    }
}

// ---------------------------------------------------------------------------
extern "C" void kernel_launch(void* const* d_in, const int* in_sizes, int n_in,
                              void* d_out, int out_size) {
    const float* z_e      = (const float*)d_in[0];
    const float* codebook = (const float*)d_in[1];
    float* out = (float*)d_out;

    static bool attr_set = false;
    if (!attr_set) {
        cudaFuncSetAttribute(vq_mma_kernel,
                             cudaFuncAttributeMaxDynamicSharedMemorySize, VQ_SMEM);
        attr_set = true;
    }

    prep_codebook<<<1, 1024>>>(codebook);
    z_split_kernel<<<NSAMP / 128, 128>>>(z_e);
    vq_mma_kernel<<<dim3(512, 2), 512, VQ_SMEM>>>();
    idx_final_kernel<<<NSAMP / 512, 512>>>(out + IDX_OFF);
    zq_loss_kernel<<<dim3(DIM, BSZ), 256>>>(z_e, codebook, out);
    finalize_kernel<<<1, 1024>>>(out);
}